// round 12
// baseline (speedup 1.0000x reference)
#include <cuda_runtime.h>
#include <cuda_bf16.h>
#include <cstdint>
#include <math.h>

// ---------------- problem constants ----------------
#define PDIM   128              // n_proxy_sets
#define EDIM   32               // elements per proxy set
#define DDIM   64               // feature dim
#define PE     (PDIM*EDIM)      // 4096 flattened proxies
#define NCH_CTA 32              // chunks per CTA (32 proxies = 1 set each; 4 CTAs/segment)
#define TILE_M 128              // x rows per tile
#define XPITCH 72               // padded bf16 row pitch (conflict-free ldsm)
#define THREADS 256
#define MAXB   1024

// W pre-shuffled into per-thread mma-fragment order (layout identical to R9):
// uint4 index = (set*8 + f)*32 + lane,  set 0..127, f = nl*2 + half
// uint4 = {b0(k16=2h), b1(k16=2h), b0(k16=2h+1), b1(k16=2h+1)} for (lane,nl)
__device__ uint4 g_wfrag[PE * DDIM / 8];     // 512 KB (L2-hot)
__device__ int g_segoff[MAXB];

// ---------------- prep kernel: fragment-shuffle conversion + scan ----------------
__global__ void prep_kernel(const float* __restrict__ w,
                            const int* __restrict__ index, int B) {
    if (blockIdx.x < 128) {
        int id   = blockIdx.x * 256 + threadIdx.x;   // 0..32767 uint4s
        int lane = id & 31;
        int f    = (id >> 5) & 7;
        int cpg  = id >> 8;                          // set 0..127
        int nl   = f >> 1, half = f & 1;
        int g    = lane >> 2, t = lane & 3;
        const float* wr = w + ((size_t)(cpg * 32 + nl * 8 + g)) * DDIM;
        int ka = half * 32;                          // k16=(2*half)*16
        __nv_bfloat162 x = __floats2bfloat162_rn(wr[ka +      t*2], wr[ka +      t*2 + 1]);
        __nv_bfloat162 y = __floats2bfloat162_rn(wr[ka +  8 + t*2], wr[ka +  8 + t*2 + 1]);
        __nv_bfloat162 z = __floats2bfloat162_rn(wr[ka + 16 + t*2], wr[ka + 16 + t*2 + 1]);
        __nv_bfloat162 u = __floats2bfloat162_rn(wr[ka + 24 + t*2], wr[ka + 24 + t*2 + 1]);
        uint4 pk;
        pk.x = *(uint32_t*)&x; pk.y = *(uint32_t*)&y;
        pk.z = *(uint32_t*)&z; pk.w = *(uint32_t*)&u;
        g_wfrag[id] = pk;
    } else {
        __shared__ int s[256];
        int t = threadIdx.x;
        int v[4]; int base = t * 4;
        int acc = 0;
        #pragma unroll
        for (int j = 0; j < 4; ++j) {
            v[j] = acc;
            int e = base + j;
            acc += (e < B) ? index[e] : 0;
        }
        s[t] = acc;
        __syncthreads();
        for (int o = 1; o < 256; o <<= 1) {
            int add = (t >= o) ? s[t - o] : 0;
            __syncthreads();
            s[t] += add;
            __syncthreads();
        }
        int pre = (t > 0) ? s[t - 1] : 0;
        #pragma unroll
        for (int j = 0; j < 4; ++j) {
            int e = base + j;
            if (e < B) g_segoff[e] = pre + v[j];
        }
    }
}

// ---------------- MMA primitives ----------------
__device__ __forceinline__ void ldsm_x4(uint32_t& r0, uint32_t& r1,
                                        uint32_t& r2, uint32_t& r3,
                                        const void* p) {
    uint32_t a = (uint32_t)__cvta_generic_to_shared(p);
    asm volatile("ldmatrix.sync.aligned.m8n8.x4.shared.b16 {%0,%1,%2,%3}, [%4];"
                 : "=r"(r0), "=r"(r1), "=r"(r2), "=r"(r3) : "r"(a));
}

__device__ __forceinline__ void mma_bf16(float* c, const uint32_t* a,
                                         uint32_t b0, uint32_t b1) {
    asm volatile(
        "mma.sync.aligned.m16n8k16.row.col.f32.bf16.bf16.f32 "
        "{%0,%1,%2,%3}, {%4,%5,%6,%7}, {%8,%9}, {%0,%1,%2,%3};"
        : "+f"(c[0]), "+f"(c[1]), "+f"(c[2]), "+f"(c[3])
        : "r"(a[0]), "r"(a[1]), "r"(a[2]), "r"(a[3]), "r"(b0), "r"(b1));
}

// one 16-col stage, M=16: 8 HMMAs from fragment-direct B regs, fold into rm[2]
__device__ __forceinline__ void stage_compute(const uint4* bb,
                                              const uint32_t afr[4][4],
                                              float rm[2], bool first) {
    float acc[2][4];
    #pragma unroll
    for (int nlh = 0; nlh < 2; ++nlh)
        acc[nlh][0] = acc[nlh][1] = acc[nlh][2] = acc[nlh][3] = 0.f;

    #pragma unroll
    for (int k16 = 0; k16 < 4; ++k16) {
        #pragma unroll
        for (int nlh = 0; nlh < 2; ++nlh) {
            uint4 v = bb[nlh * 2 + (k16 >> 1)];
            uint32_t b0 = (k16 & 1) ? v.z : v.x;
            uint32_t b1 = (k16 & 1) ? v.w : v.y;
            mma_bf16(acc[nlh], afr[k16], b0, b1);
        }
    }
    float lo = fmaxf(fmaxf(acc[0][0], acc[0][1]), fmaxf(acc[1][0], acc[1][1]));
    float hi = fmaxf(fmaxf(acc[0][2], acc[0][3]), fmaxf(acc[1][2], acc[1][3]));
    if (first) { rm[0] = lo; rm[1] = hi; }
    else       { rm[0] = fmaxf(rm[0], lo); rm[1] = fmaxf(rm[1], hi); }
}

#define LOAD4(dst, ptr) do {                     \
    (dst)[0] = __ldg((ptr));                     \
    (dst)[1] = __ldg((ptr) + 32);                \
    (dst)[2] = __ldg((ptr) + 64);                \
    (dst)[3] = __ldg((ptr) + 96); } while (0)

// ---------------- main kernel ----------------
// 4 CTAs per segment (blockIdx = b*4 + quarter); each sweeps 32 chunks of 32
// proxies (1 set/chunk). 8 warps = 8 row-groups of 16 rows; every warp covers
// the chunk's full 32 cols in 2 stages of 16. Slim registers (~75/thread) ->
// 3 CTAs/SM, 24 warps for latency hiding. B fragments streamed from L2 via
// LDG.128, barrier-free chunk loop with R9's exact schedule shape.
__global__ __launch_bounds__(THREADS, 3)
void main_kernel(const float* __restrict__ x, const int* __restrict__ index,
                 float* __restrict__ out) {
    __shared__ __nv_bfloat16 xs[TILE_M * XPITCH];   // 18 KB
    __shared__ float pooled2[32 * 64];              // 8 KB [p_local][slot]

    const int b       = blockIdx.x >> 2;
    const int quarter = blockIdx.x & 3;
    const int tid  = threadIdx.x;
    const int lane = tid & 31;
    const int rgrp = tid >> 5;     // row-group: 16 rows per warp

    for (int i = tid; i < 32 * 64; i += THREADS) pooled2[i] = 0.f;

    const int off = g_segoff[b];
    const int len = index[b];

    // this warp's fragment stream: quarter selects 32 sets; set stride 256 u4
    const uint4* wf = g_wfrag + (size_t)quarter * 8192 + lane;

    for (int tile = 0; tile * TILE_M < len; ++tile) {
        __syncthreads();   // pooled2 init / previous tile xs drain
        // ---- stage x tile to bf16 smem (zero-pad ragged tail) ----
        {
            int row  = tid >> 1;
            int hh   = tid & 1;
            int rrem = len - tile * TILE_M;
            bool valid = row < rrem;
            const float* xr = x + ((size_t)(off + tile * TILE_M + row)) * DDIM + hh * 32;
            __nv_bfloat162* dst = (__nv_bfloat162*)&xs[row * XPITCH + hh * 32];
            #pragma unroll
            for (int j = 0; j < 8; ++j) {
                float4 v = valid ? __ldg((const float4*)xr + j)
                                 : make_float4(0.f, 0.f, 0.f, 0.f);
                dst[2 * j]     = __floats2bfloat162_rn(v.x, v.y);
                dst[2 * j + 1] = __floats2bfloat162_rn(v.z, v.w);
            }
        }
        __syncthreads();   // xs visible

        // ---- A fragments: 16 rows per warp, pinned across all chunks ----
        uint32_t afr[4][4];
        {
            const __nv_bfloat16* base =
                &xs[(rgrp * 16 + (lane & 15)) * XPITCH + (lane >> 4) * 8];
            #pragma unroll
            for (int k = 0; k < 4; ++k)
                ldsm_x4(afr[k][0], afr[k][1], afr[k][2], afr[k][3],
                        base + k * 16);
        }

        // ---- barrier-free chunk sweep, 2-stage register pipeline (R9 shape) ----
        uint4 bufA[4], bufB[4];
        LOAD4(bufA, wf);                      // chunk 0, stage 0
        for (int c = 0; c < NCH_CTA; ++c) {
            const uint4* cbase = wf + c * 256;
            // prefetch stage 1 of chunk c, then compute stage 0
            LOAD4(bufB, cbase + 128);
            float rm[2];
            stage_compute(bufA, afr, rm, true);
            // prefetch stage 0 of chunk c+1, then compute stage 1
            if (c + 1 < NCH_CTA) LOAD4(bufA, cbase + 256);
            stage_compute(bufB, afr, rm, false);

            // quad-max per row (covers all 32 cols of this set)
            rm[0] = fmaxf(rm[0], __shfl_xor_sync(0xffffffffu, rm[0], 1));
            rm[1] = fmaxf(rm[1], __shfl_xor_sync(0xffffffffu, rm[1], 1));
            rm[0] = fmaxf(rm[0], __shfl_xor_sync(0xffffffffu, rm[0], 2));
            rm[1] = fmaxf(rm[1], __shfl_xor_sync(0xffffffffu, rm[1], 2));
            float s2 = rm[0] + rm[1];          // rows g and g+8 of this warp
            // exclusive-owner accumulate (no atomics, no shuffle-to-lane0)
            if ((lane & 3) == 0)
                pooled2[c * 64 + rgrp * 8 + (lane >> 2)] += s2;
        }
    }

    // ---- CTA-end reduction: 32 p x 64 slots -> out (unnormalized) ----
    __syncthreads();
    {
        int pl = tid >> 3, j = tid & 7;       // 32 p x 8 reducers
        const float* row = &pooled2[pl * 64 + j * 8];
        float s = 0.f;
        #pragma unroll
        for (int k = 0; k < 8; ++k) s += row[k];
        s += __shfl_xor_sync(0xffffffffu, s, 1);
        s += __shfl_xor_sync(0xffffffffu, s, 2);
        s += __shfl_xor_sync(0xffffffffu, s, 4);
        if (j == 0) out[(size_t)b * PDIM + quarter * 32 + pl] = s;
    }
}

// ---------------- normalize kernel ----------------
__global__ void norm_kernel(float* __restrict__ out) {
    __shared__ float red[4];
    int b = blockIdx.x, t = threadIdx.x;   // 128 threads
    float v = out[(size_t)b * PDIM + t];
    float s2 = v * v;
    #pragma unroll
    for (int o = 16; o > 0; o >>= 1) s2 += __shfl_xor_sync(0xffffffffu, s2, o);
    if ((t & 31) == 0) red[t >> 5] = s2;
    __syncthreads();
    float nrm = sqrtf(red[0] + red[1] + red[2] + red[3]);
    out[(size_t)b * PDIM + t] = v / fmaxf(nrm, 1e-12f);
}

// ---------------- launch ----------------
extern "C" void kernel_launch(void* const* d_in, const int* in_sizes, int n_in,
                              void* d_out, int out_size) {
    const float* x     = (const float*)d_in[0];
    const float* w     = (const float*)d_in[1];
    const int*   index = (const int*)d_in[2];
    float* out = (float*)d_out;

    int B = in_sizes[2];             // 1024

    prep_kernel<<<129, 256>>>(w, index, B);
    main_kernel<<<4 * B, THREADS>>>(x, index, out);
    norm_kernel<<<B, 128>>>(out);
}

// round 16
// speedup vs baseline: 1.1619x; 1.1619x over previous
#include <cuda_runtime.h>
#include <cuda_bf16.h>
#include <cstdint>
#include <math.h>

// ---------------- problem constants ----------------
#define PDIM   128              // n_proxy_sets
#define EDIM   32               // elements per proxy set
#define DDIM   64               // feature dim
#define PE     (PDIM*EDIM)      // 4096 flattened proxies
#define NCH_CTA 32              // chunks per CTA (64 proxies each; 2 CTAs/segment)
#define TILE_M 128              // x rows per tile
#define XPITCH 72               // padded bf16 row pitch (conflict-free ldsm)
#define THREADS 256
#define MAXB   1024

// W pre-shuffled into per-thread mma-fragment order:
// uint4 index = ((cpg)*8 + f)*32 + lane,  cpg = chunk*2+pg (0..127), f = nl*2+half
// uint4 = {b0(k16=2h), b1(k16=2h), b0(k16=2h+1), b1(k16=2h+1)} for (lane,nl)
__device__ uint4 g_wfrag[PE * DDIM / 8];     // 512 KB (L2-hot)
__device__ int g_segoff[MAXB];

// ---------------- prep kernel: fragment-shuffle conversion + scan ----------------
__global__ void prep_kernel(const float* __restrict__ w,
                            const int* __restrict__ index, int B) {
    if (blockIdx.x < 128) {
        int id   = blockIdx.x * 256 + threadIdx.x;   // 0..32767 uint4s
        int lane = id & 31;
        int f    = (id >> 5) & 7;
        int cpg  = id >> 8;                          // 0..127
        int nl   = f >> 1, half = f & 1;
        int g    = lane >> 2, t = lane & 3;
        const float* wr = w + ((size_t)(cpg * 32 + nl * 8 + g)) * DDIM;
        int ka = half * 32;                          // k16=(2*half)*16
        __nv_bfloat162 x = __floats2bfloat162_rn(wr[ka +      t*2], wr[ka +      t*2 + 1]);
        __nv_bfloat162 y = __floats2bfloat162_rn(wr[ka +  8 + t*2], wr[ka +  8 + t*2 + 1]);
        __nv_bfloat162 z = __floats2bfloat162_rn(wr[ka + 16 + t*2], wr[ka + 16 + t*2 + 1]);
        __nv_bfloat162 u = __floats2bfloat162_rn(wr[ka + 24 + t*2], wr[ka + 24 + t*2 + 1]);
        uint4 pk;
        pk.x = *(uint32_t*)&x; pk.y = *(uint32_t*)&y;
        pk.z = *(uint32_t*)&z; pk.w = *(uint32_t*)&u;
        g_wfrag[id] = pk;
    } else {
        __shared__ int s[256];
        int t = threadIdx.x;
        int v[4]; int base = t * 4;
        int acc = 0;
        #pragma unroll
        for (int j = 0; j < 4; ++j) {
            v[j] = acc;
            int e = base + j;
            acc += (e < B) ? index[e] : 0;
        }
        s[t] = acc;
        __syncthreads();
        for (int o = 1; o < 256; o <<= 1) {
            int add = (t >= o) ? s[t - o] : 0;
            __syncthreads();
            s[t] += add;
            __syncthreads();
        }
        int pre = (t > 0) ? s[t - 1] : 0;
        #pragma unroll
        for (int j = 0; j < 4; ++j) {
            int e = base + j;
            if (e < B) g_segoff[e] = pre + v[j];
        }
    }
}

// ---------------- MMA primitives ----------------
__device__ __forceinline__ void ldsm_x4(uint32_t& r0, uint32_t& r1,
                                        uint32_t& r2, uint32_t& r3,
                                        const void* p) {
    uint32_t a = (uint32_t)__cvta_generic_to_shared(p);
    asm volatile("ldmatrix.sync.aligned.m8n8.x4.shared.b16 {%0,%1,%2,%3}, [%4];"
                 : "=r"(r0), "=r"(r1), "=r"(r2), "=r"(r3) : "r"(a));
}

__device__ __forceinline__ void mma_bf16(float* c, const uint32_t* a,
                                         uint32_t b0, uint32_t b1) {
    asm volatile(
        "mma.sync.aligned.m16n8k16.row.col.f32.bf16.bf16.f32 "
        "{%0,%1,%2,%3}, {%4,%5,%6,%7}, {%8,%9}, {%0,%1,%2,%3};"
        : "+f"(c[0]), "+f"(c[1]), "+f"(c[2]), "+f"(c[3])
        : "r"(a[0]), "r"(a[1]), "r"(a[2]), "r"(a[3]), "r"(b0), "r"(b1));
}

// one 16-col stage: 16 HMMAs from fragment-direct B regs, fold into rm
__device__ __forceinline__ void stage_compute(const uint4* bb,
                                              const uint32_t afr[2][4][4],
                                              float rm[4], bool first) {
    float acc[2][2][4];
    #pragma unroll
    for (int m = 0; m < 2; ++m)
        #pragma unroll
        for (int nlh = 0; nlh < 2; ++nlh)
            acc[m][nlh][0] = acc[m][nlh][1] = acc[m][nlh][2] = acc[m][nlh][3] = 0.f;

    #pragma unroll
    for (int k16 = 0; k16 < 4; ++k16) {
        #pragma unroll
        for (int nlh = 0; nlh < 2; ++nlh) {
            uint4 v = bb[nlh * 2 + (k16 >> 1)];
            uint32_t b0 = (k16 & 1) ? v.z : v.x;
            uint32_t b1 = (k16 & 1) ? v.w : v.y;
            mma_bf16(acc[0][nlh], afr[0][k16], b0, b1);
            mma_bf16(acc[1][nlh], afr[1][k16], b0, b1);
        }
    }
    #pragma unroll
    for (int m = 0; m < 2; ++m) {
        float lo = fmaxf(fmaxf(acc[m][0][0], acc[m][0][1]),
                         fmaxf(acc[m][1][0], acc[m][1][1]));
        float hi = fmaxf(fmaxf(acc[m][0][2], acc[m][0][3]),
                         fmaxf(acc[m][1][2], acc[m][1][3]));
        if (first) { rm[m * 2] = lo; rm[m * 2 + 1] = hi; }
        else       { rm[m * 2] = fmaxf(rm[m * 2], lo);
                     rm[m * 2 + 1] = fmaxf(rm[m * 2 + 1], hi); }
    }
}

#define LOAD4(dst, ptr) do {                     \
    (dst)[0] = __ldg((ptr));                     \
    (dst)[1] = __ldg((ptr) + 32);                \
    (dst)[2] = __ldg((ptr) + 64);                \
    (dst)[3] = __ldg((ptr) + 96); } while (0)

// ---------------- main kernel ----------------
// 2 CTAs per segment; each sweeps 32 proxy chunks. 8 warps = 4 rgrp x 2 pg.
// B fragments read DIRECTLY from g_wfrag via coalesced LDG.128 (no smem, no
// barriers in chunk loop), 2-stage register pipeline — R9's exact schedule —
// but chunks processed in PAIRS with both chunks' shuffle reductions batched
// at pair end (8 independent SHFL chains pipeline instead of 2 serial tails).
__global__ __launch_bounds__(THREADS, 2)
void main_kernel(const float* __restrict__ x, const int* __restrict__ index,
                 float* __restrict__ out) {
    __shared__ __nv_bfloat16 xs[TILE_M * XPITCH];   // 18 KB
    __shared__ float pooled2[64 * 32];              // 8 KB [p_local][slot]

    const int b    = blockIdx.x >> 1;
    const int half = blockIdx.x & 1;
    const int tid  = threadIdx.x;
    const int lane = tid & 31;
    const int warp = tid >> 5;
    const int rgrp = warp & 3;     // row-group (32 rows)
    const int pg   = warp >> 2;    // proxy-group within chunk (0/1)

    for (int i = tid; i < 64 * 32; i += THREADS) pooled2[i] = 0.f;

    const int off = g_segoff[b];
    const int len = index[b];

    // this warp's fragment stream: half selects 32-chunk range; chunk stride 512 u4
    const uint4* wf = g_wfrag + (size_t)half * 16384 + pg * 256 + lane;

    for (int tile = 0; tile * TILE_M < len; ++tile) {
        __syncthreads();   // pooled2 init / previous tile xs drain
        // ---- stage x tile to bf16 smem (zero-pad ragged tail), vector STS ----
        {
            int row  = tid >> 1;
            int hh   = tid & 1;
            int rrem = len - tile * TILE_M;
            bool valid = row < rrem;
            const float* xr = x + ((size_t)(off + tile * TILE_M + row)) * DDIM + hh * 32;
            uint32_t wd[16];
            #pragma unroll
            for (int j = 0; j < 8; ++j) {
                float4 v = valid ? __ldg((const float4*)xr + j)
                                 : make_float4(0.f, 0.f, 0.f, 0.f);
                __nv_bfloat162 h0 = __floats2bfloat162_rn(v.x, v.y);
                __nv_bfloat162 h1 = __floats2bfloat162_rn(v.z, v.w);
                wd[2 * j]     = *(uint32_t*)&h0;
                wd[2 * j + 1] = *(uint32_t*)&h1;
            }
            uint4* du = (uint4*)&xs[row * XPITCH + hh * 32];   // 16B-aligned
            #pragma unroll
            for (int j = 0; j < 4; ++j) {
                uint4 pk;
                pk.x = wd[4 * j]; pk.y = wd[4 * j + 1];
                pk.z = wd[4 * j + 2]; pk.w = wd[4 * j + 3];
                du[j] = pk;
            }
        }
        __syncthreads();   // xs visible

        // ---- A fragments: 32 rows per warp, pinned across all chunks ----
        uint32_t afr[2][4][4];
        #pragma unroll
        for (int m = 0; m < 2; ++m) {
            const __nv_bfloat16* base =
                &xs[(rgrp * 32 + m * 16 + (lane & 15)) * XPITCH + (lane >> 4) * 8];
            #pragma unroll
            for (int k = 0; k < 4; ++k)
                ldsm_x4(afr[m][k][0], afr[m][k][1], afr[m][k][2], afr[m][k][3],
                        base + k * 16);
        }

        // ---- barrier-free chunk sweep in PAIRS (R9 load/compute interleave) ----
        uint4 bufA[4], bufB[4];
        LOAD4(bufA, wf);                      // chunk 0, stage 0
        for (int cp = 0; cp < NCH_CTA; cp += 2) {
            const uint4* cb0 = wf + cp * 512;
            const uint4* cb1 = cb0 + 512;
            float rm0[4], rm1[4];
            // chunk cp
            LOAD4(bufB, cb0 + 128);           // cp stage 1
            stage_compute(bufA, afr, rm0, true);
            LOAD4(bufA, cb1);                 // (cp+1) stage 0
            stage_compute(bufB, afr, rm0, false);
            // chunk cp+1
            LOAD4(bufB, cb1 + 128);           // (cp+1) stage 1
            stage_compute(bufA, afr, rm1, true);
            if (cp + 2 < NCH_CTA) LOAD4(bufA, cb0 + 1024);  // (cp+2) stage 0
            stage_compute(bufB, afr, rm1, false);

            // batched quad-max reductions: 8 independent chains pipeline
            #pragma unroll
            for (int r = 0; r < 4; ++r) {
                rm0[r] = fmaxf(rm0[r], __shfl_xor_sync(0xffffffffu, rm0[r], 1));
                rm1[r] = fmaxf(rm1[r], __shfl_xor_sync(0xffffffffu, rm1[r], 1));
            }
            #pragma unroll
            for (int r = 0; r < 4; ++r) {
                rm0[r] = fmaxf(rm0[r], __shfl_xor_sync(0xffffffffu, rm0[r], 2));
                rm1[r] = fmaxf(rm1[r], __shfl_xor_sync(0xffffffffu, rm1[r], 2));
            }
            float s40 = (rm0[0] + rm0[1]) + (rm0[2] + rm0[3]);
            float s41 = (rm1[0] + rm1[1]) + (rm1[2] + rm1[3]);
            if ((lane & 3) == 0) {
                int slot = rgrp * 8 + (lane >> 2);
                pooled2[(cp * 2 + pg) * 32 + slot]       += s40;
                pooled2[((cp + 1) * 2 + pg) * 32 + slot] += s41;
            }
        }
    }

    // ---- CTA-end reduction: 64 p x 32 slots -> out (unnormalized) ----
    __syncthreads();
    {
        int pl = tid >> 2, q = tid & 3;
        const float* row = &pooled2[pl * 32 + q * 8];
        float s = 0.f;
        #pragma unroll
        for (int j = 0; j < 8; ++j) s += row[j];
        s += __shfl_xor_sync(0xffffffffu, s, 1);
        s += __shfl_xor_sync(0xffffffffu, s, 2);
        if (q == 0) out[(size_t)b * PDIM + half * 64 + pl] = s;
    }
}

// ---------------- normalize kernel ----------------
__global__ void norm_kernel(float* __restrict__ out) {
    __shared__ float red[4];
    int b = blockIdx.x, t = threadIdx.x;   // 128 threads
    float v = out[(size_t)b * PDIM + t];
    float s2 = v * v;
    #pragma unroll
    for (int o = 16; o > 0; o >>= 1) s2 += __shfl_xor_sync(0xffffffffu, s2, o);
    if ((t & 31) == 0) red[t >> 5] = s2;
    __syncthreads();
    float nrm = sqrtf(red[0] + red[1] + red[2] + red[3]);
    out[(size_t)b * PDIM + t] = v / fmaxf(nrm, 1e-12f);
}

// ---------------- launch ----------------
extern "C" void kernel_launch(void* const* d_in, const int* in_sizes, int n_in,
                              void* d_out, int out_size) {
    const float* x     = (const float*)d_in[0];
    const float* w     = (const float*)d_in[1];
    const int*   index = (const int*)d_in[2];
    float* out = (float*)d_out;

    int B = in_sizes[2];             // 1024

    prep_kernel<<<129, 256>>>(w, index, B);
    main_kernel<<<2 * B, THREADS>>>(x, index, out);
    norm_kernel<<<B, 128>>>(out);
}

// round 17
// speedup vs baseline: 1.1636x; 1.0015x over previous
#include <cuda_runtime.h>
#include <cuda_bf16.h>
#include <cstdint>
#include <math.h>

// ---------------- problem constants ----------------
#define PDIM   128              // n_proxy_sets
#define EDIM   32               // elements per proxy set
#define DDIM   64               // feature dim
#define PE     (PDIM*EDIM)      // 4096 flattened proxies
#define NCH_CTA 32              // chunks per CTA (64 proxies each; 2 CTAs/segment)
#define TILE_M 128              // x rows per tile
#define XPITCH 72               // padded bf16 row pitch (conflict-free ldsm)
#define THREADS 256
#define MAXB   1024

// W pre-shuffled into per-thread mma-fragment order:
// uint4 index = ((cpg)*8 + f)*32 + lane,  cpg = chunk*2+pg (0..127), f = nl*2+half
// uint4 = {b0(k16=2h), b1(k16=2h), b0(k16=2h+1), b1(k16=2h+1)} for (lane,nl)
__device__ uint4 g_wfrag[PE * DDIM / 8];     // 512 KB (L2-hot)
__device__ int g_segoff[MAXB];
__device__ int g_done[MAXB];                 // per-segment arrival counter

// ---------------- prep kernel: fragment-shuffle conversion + scan + counter reset ----------------
__global__ void prep_kernel(const float* __restrict__ w,
                            const int* __restrict__ index, int B) {
    if (blockIdx.x < 128) {
        int id   = blockIdx.x * 256 + threadIdx.x;   // 0..32767 uint4s
        int lane = id & 31;
        int f    = (id >> 5) & 7;
        int cpg  = id >> 8;                          // 0..127
        int nl   = f >> 1, half = f & 1;
        int g    = lane >> 2, t = lane & 3;
        const float* wr = w + ((size_t)(cpg * 32 + nl * 8 + g)) * DDIM;
        int ka = half * 32;                          // k16=(2*half)*16
        __nv_bfloat162 x = __floats2bfloat162_rn(wr[ka +      t*2], wr[ka +      t*2 + 1]);
        __nv_bfloat162 y = __floats2bfloat162_rn(wr[ka +  8 + t*2], wr[ka +  8 + t*2 + 1]);
        __nv_bfloat162 z = __floats2bfloat162_rn(wr[ka + 16 + t*2], wr[ka + 16 + t*2 + 1]);
        __nv_bfloat162 u = __floats2bfloat162_rn(wr[ka + 24 + t*2], wr[ka + 24 + t*2 + 1]);
        uint4 pk;
        pk.x = *(uint32_t*)&x; pk.y = *(uint32_t*)&y;
        pk.z = *(uint32_t*)&z; pk.w = *(uint32_t*)&u;
        g_wfrag[id] = pk;
    } else {
        __shared__ int s[256];
        int t = threadIdx.x;
        int v[4]; int base = t * 4;
        int acc = 0;
        #pragma unroll
        for (int j = 0; j < 4; ++j) {
            v[j] = acc;
            int e = base + j;
            acc += (e < B) ? index[e] : 0;
        }
        s[t] = acc;
        __syncthreads();
        for (int o = 1; o < 256; o <<= 1) {
            int add = (t >= o) ? s[t - o] : 0;
            __syncthreads();
            s[t] += add;
            __syncthreads();
        }
        int pre = (t > 0) ? s[t - 1] : 0;
        #pragma unroll
        for (int j = 0; j < 4; ++j) {
            int e = base + j;
            if (e < B) { g_segoff[e] = pre + v[j]; g_done[e] = 0; }
        }
    }
}

// ---------------- MMA primitives ----------------
__device__ __forceinline__ void ldsm_x4(uint32_t& r0, uint32_t& r1,
                                        uint32_t& r2, uint32_t& r3,
                                        const void* p) {
    uint32_t a = (uint32_t)__cvta_generic_to_shared(p);
    asm volatile("ldmatrix.sync.aligned.m8n8.x4.shared.b16 {%0,%1,%2,%3}, [%4];"
                 : "=r"(r0), "=r"(r1), "=r"(r2), "=r"(r3) : "r"(a));
}

__device__ __forceinline__ void mma_bf16(float* c, const uint32_t* a,
                                         uint32_t b0, uint32_t b1) {
    asm volatile(
        "mma.sync.aligned.m16n8k16.row.col.f32.bf16.bf16.f32 "
        "{%0,%1,%2,%3}, {%4,%5,%6,%7}, {%8,%9}, {%0,%1,%2,%3};"
        : "+f"(c[0]), "+f"(c[1]), "+f"(c[2]), "+f"(c[3])
        : "r"(a[0]), "r"(a[1]), "r"(a[2]), "r"(a[3]), "r"(b0), "r"(b1));
}

// one 16-col stage: 16 HMMAs from fragment-direct B regs, fold into rm
__device__ __forceinline__ void stage_compute(const uint4* bb,
                                              const uint32_t afr[2][4][4],
                                              float rm[4], bool first) {
    float acc[2][2][4];
    #pragma unroll
    for (int m = 0; m < 2; ++m)
        #pragma unroll
        for (int nlh = 0; nlh < 2; ++nlh)
            acc[m][nlh][0] = acc[m][nlh][1] = acc[m][nlh][2] = acc[m][nlh][3] = 0.f;

    #pragma unroll
    for (int k16 = 0; k16 < 4; ++k16) {
        #pragma unroll
        for (int nlh = 0; nlh < 2; ++nlh) {
            uint4 v = bb[nlh * 2 + (k16 >> 1)];
            uint32_t b0 = (k16 & 1) ? v.z : v.x;
            uint32_t b1 = (k16 & 1) ? v.w : v.y;
            mma_bf16(acc[0][nlh], afr[0][k16], b0, b1);
            mma_bf16(acc[1][nlh], afr[1][k16], b0, b1);
        }
    }
    #pragma unroll
    for (int m = 0; m < 2; ++m) {
        float lo = fmaxf(fmaxf(acc[m][0][0], acc[m][0][1]),
                         fmaxf(acc[m][1][0], acc[m][1][1]));
        float hi = fmaxf(fmaxf(acc[m][0][2], acc[m][0][3]),
                         fmaxf(acc[m][1][2], acc[m][1][3]));
        if (first) { rm[m * 2] = lo; rm[m * 2 + 1] = hi; }
        else       { rm[m * 2] = fmaxf(rm[m * 2], lo);
                     rm[m * 2 + 1] = fmaxf(rm[m * 2 + 1], hi); }
    }
}

#define LOAD4(dst, ptr) do {                     \
    (dst)[0] = __ldg((ptr));                     \
    (dst)[1] = __ldg((ptr) + 32);                \
    (dst)[2] = __ldg((ptr) + 64);                \
    (dst)[3] = __ldg((ptr) + 96); } while (0)

// ---------------- main kernel ----------------
// 2 CTAs per segment; each sweeps 32 proxy chunks. 8 warps = 4 rgrp x 2 pg.
// B fragments read DIRECTLY from g_wfrag via coalesced LDG.128 (no smem, no
// barriers in chunk loop), 2-stage register pipeline (R9's exact schedule).
// The LAST-arriving CTA of each segment performs the L2 normalization in-place
// (fused norm_kernel), replicating its exact reduction order.
__global__ __launch_bounds__(THREADS, 2)
void main_kernel(const float* __restrict__ x, const int* __restrict__ index,
                 float* __restrict__ out) {
    __shared__ __nv_bfloat16 xs[TILE_M * XPITCH];   // 18 KB
    __shared__ float pooled2[64 * 32];              // 8 KB [p_local][slot]
    __shared__ float red[8];
    __shared__ int amLast;

    const int b    = blockIdx.x >> 1;
    const int half = blockIdx.x & 1;
    const int tid  = threadIdx.x;
    const int lane = tid & 31;
    const int warp = tid >> 5;
    const int rgrp = warp & 3;     // row-group (32 rows)
    const int pg   = warp >> 2;    // proxy-group within chunk (0/1)

    for (int i = tid; i < 64 * 32; i += THREADS) pooled2[i] = 0.f;

    const int off = g_segoff[b];
    const int len = index[b];

    // this warp's fragment stream: half selects 32-chunk range; chunk stride 512 u4
    const uint4* wf = g_wfrag + (size_t)half * 16384 + pg * 256 + lane;

    for (int tile = 0; tile * TILE_M < len; ++tile) {
        __syncthreads();   // pooled2 init / previous tile xs drain
        // ---- stage x tile to bf16 smem (zero-pad ragged tail), vector STS ----
        {
            int row  = tid >> 1;
            int hh   = tid & 1;
            int rrem = len - tile * TILE_M;
            bool valid = row < rrem;
            const float* xr = x + ((size_t)(off + tile * TILE_M + row)) * DDIM + hh * 32;
            uint32_t wd[16];
            #pragma unroll
            for (int j = 0; j < 8; ++j) {
                float4 v = valid ? __ldg((const float4*)xr + j)
                                 : make_float4(0.f, 0.f, 0.f, 0.f);
                __nv_bfloat162 h0 = __floats2bfloat162_rn(v.x, v.y);
                __nv_bfloat162 h1 = __floats2bfloat162_rn(v.z, v.w);
                wd[2 * j]     = *(uint32_t*)&h0;
                wd[2 * j + 1] = *(uint32_t*)&h1;
            }
            uint4* du = (uint4*)&xs[row * XPITCH + hh * 32];   // 16B-aligned
            #pragma unroll
            for (int j = 0; j < 4; ++j) {
                uint4 pk;
                pk.x = wd[4 * j]; pk.y = wd[4 * j + 1];
                pk.z = wd[4 * j + 2]; pk.w = wd[4 * j + 3];
                du[j] = pk;
            }
        }
        __syncthreads();   // xs visible

        // ---- A fragments: 32 rows per warp, pinned across all chunks ----
        uint32_t afr[2][4][4];
        #pragma unroll
        for (int m = 0; m < 2; ++m) {
            const __nv_bfloat16* base =
                &xs[(rgrp * 32 + m * 16 + (lane & 15)) * XPITCH + (lane >> 4) * 8];
            #pragma unroll
            for (int k = 0; k < 4; ++k)
                ldsm_x4(afr[m][k][0], afr[m][k][1], afr[m][k][2], afr[m][k][3],
                        base + k * 16);
        }

        // ---- barrier-free chunk sweep, 2-stage register pipeline (R9 exact) ----
        uint4 bufA[4], bufB[4];
        LOAD4(bufA, wf);                      // chunk 0, stage 0
        for (int c = 0; c < NCH_CTA; ++c) {
            const uint4* cbase = wf + c * 512;
            // prefetch stage 1 of chunk c, then compute stage 0
            LOAD4(bufB, cbase + 128);
            float rm[4];
            stage_compute(bufA, afr, rm, true);
            // prefetch stage 0 of chunk c+1, then compute stage 1
            if (c + 1 < NCH_CTA) LOAD4(bufA, cbase + 512);
            stage_compute(bufB, afr, rm, false);

            // quad-max per row (covers all 32 cols of this p-group)
            #pragma unroll
            for (int r = 0; r < 4; ++r) {
                rm[r] = fmaxf(rm[r], __shfl_xor_sync(0xffffffffu, rm[r], 1));
                rm[r] = fmaxf(rm[r], __shfl_xor_sync(0xffffffffu, rm[r], 2));
            }
            float s4 = (rm[0] + rm[1]) + (rm[2] + rm[3]);   // 4 rows, this thread
            // exclusive-owner accumulate (no atomics, no shuffle-to-lane0)
            if ((lane & 3) == 0)
                pooled2[(c * 2 + pg) * 32 + rgrp * 8 + (lane >> 2)] += s4;
        }
    }

    // ---- CTA-end reduction: 64 p x 32 slots -> out (unnormalized) ----
    __syncthreads();
    {
        int pl = tid >> 2, q = tid & 3;
        const float* row = &pooled2[pl * 32 + q * 8];
        float s = 0.f;
        #pragma unroll
        for (int j = 0; j < 8; ++j) s += row[j];
        s += __shfl_xor_sync(0xffffffffu, s, 1);
        s += __shfl_xor_sync(0xffffffffu, s, 2);
        if (q == 0) out[(size_t)b * PDIM + half * 64 + pl] = s;
    }

    // ---- fused normalization: last-arriving CTA of this segment ----
    __threadfence();              // our half visible before the flag
    __syncthreads();              // all writes of this CTA done
    if (tid == 0) amLast = (atomicAdd(&g_done[b], 1) == 1);
    __syncthreads();
    if (amLast) {
        __threadfence();          // order flag observation before reads
        float v = 0.f, s2 = 0.f;
        if (tid < PDIM) {
            v = __ldcg(&out[(size_t)b * PDIM + tid]);   // L2 read (skip stale L1)
            s2 = v * v;
        }
        #pragma unroll
        for (int o = 16; o > 0; o >>= 1) s2 += __shfl_xor_sync(0xffffffffu, s2, o);
        if (lane == 0) red[warp] = s2;
        __syncthreads();
        if (tid < PDIM) {
            float nrm = sqrtf(red[0] + red[1] + red[2] + red[3]);
            out[(size_t)b * PDIM + tid] = v / fmaxf(nrm, 1e-12f);
        }
    }
}

// ---------------- launch ----------------
extern "C" void kernel_launch(void* const* d_in, const int* in_sizes, int n_in,
                              void* d_out, int out_size) {
    const float* x     = (const float*)d_in[0];
    const float* w     = (const float*)d_in[1];
    const int*   index = (const int*)d_in[2];
    float* out = (float*)d_out;

    int B = in_sizes[2];             // 1024

    prep_kernel<<<129, 256>>>(w, index, B);
    main_kernel<<<2 * B, THREADS>>>(x, index, out);
}